// round 9
// baseline (speedup 1.0000x reference)
#include <cuda_runtime.h>
#include <cuda_fp16.h>
#include <cstdint>

// InstanceConv via warp-level mma.sync f16 GEMM (compute_103-safe).
// Round 9: 2-row x 128-px tiles, 2x W-fragment reuse per warp,
// cp.async.bulk (sm_90) staging of pre-swizzled input, atomic work stealing.
// B=8, C=64, OC=64, H=W=128, K=3, pad=1.

#define BATCH 8
#define CH 64
#define OCN 64
#define HDIM 128
#define WDIM 128
#define NTILES 512                   // 2-row x 128-px tiles
#define GRID_MAIN 152
#define NTHREADS 256
#define OUT_MASK_OFF (BATCH * OCN * HDIM * WDIM)   // 8388608

// ---- smem layout (bytes) ----
#define OFF_W 0
#define W_BYTES (9 * 8192)               // 73728: [tap] 64(c)x64(o) f16, swizzled
#define SLOT_B 16640                     // one X row slot: [xi:130][c:64] f16 swz
#define OFF_X (OFF_W + W_BYTES)          // 73728: 2 buffers x 4 slots
#define OFF_M (OFF_X + 8 * SLOT_B)       // 206848: 2 x mask [4][132] f32
#define MASK_BUF 2112
#define OFF_B (OFF_M + 2 * MASK_BUF)     // 211072: bias
#define OFF_CTRL (OFF_B + 256)           // 211328: [0]=next tile u32; +16/+24 mbars
#define SMEM_TOTAL (OFF_CTRL + 32)       // 211360

__device__ uint32_t g_xt[BATCH * HDIM * WDIM * 32];  // [b][y][xb:16][1KB swizzled]
__device__ uint4 g_wimg[W_BYTES / 16];
__device__ int g_ctr;

__device__ __forceinline__ uint32_t smem_u32(const void* p) {
    uint32_t a;
    asm("{ .reg .u64 t; cvta.to.shared.u64 t, %1; cvt.u32.u64 %0, t; }" : "=r"(a) : "l"(p));
    return a;
}
__device__ __forceinline__ void ldsm_x4(uint32_t addr, uint32_t* r) {
    asm volatile("ldmatrix.sync.aligned.m8n8.x4.shared.b16 {%0,%1,%2,%3}, [%4];"
                 : "=r"(r[0]), "=r"(r[1]), "=r"(r[2]), "=r"(r[3]) : "r"(addr));
}
__device__ __forceinline__ void ldsm_x4t(uint32_t addr, uint32_t& r0, uint32_t& r1,
                                         uint32_t& r2, uint32_t& r3) {
    asm volatile("ldmatrix.sync.aligned.m8n8.x4.trans.shared.b16 {%0,%1,%2,%3}, [%4];"
                 : "=r"(r0), "=r"(r1), "=r"(r2), "=r"(r3) : "r"(addr));
}
__device__ __forceinline__ void mma_f16(float* d, const uint32_t* a, uint32_t b0, uint32_t b1) {
    asm volatile("mma.sync.aligned.m16n8k16.row.col.f32.f16.f16.f32 "
                 "{%0,%1,%2,%3}, {%4,%5,%6,%7}, {%8,%9}, {%0,%1,%2,%3};"
                 : "+f"(d[0]), "+f"(d[1]), "+f"(d[2]), "+f"(d[3])
                 : "r"(a[0]), "r"(a[1]), "r"(a[2]), "r"(a[3]), "r"(b0), "r"(b1));
}
__device__ __forceinline__ void cpasync16(uint32_t d, const void* s) {
    asm volatile("cp.async.ca.shared.global [%0], [%1], 16;"
                 :: "r"(d), "l"(s) : "memory");
}
#define MBARRIER_INIT(a, n) \
    asm volatile("mbarrier.init.shared.b64 [%0], %1;" :: "r"(a), "r"((uint32_t)(n)) : "memory")
#define MBARRIER_EXPECT_TX(a, tx) \
    asm volatile("mbarrier.arrive.expect_tx.shared.b64 _, [%0], %1;" \
                 :: "r"(a), "r"((uint32_t)(tx)) : "memory")
#define MBARRIER_WAIT_PARITY(a, par) do {                                         \
    uint32_t _m = (a); uint32_t _p = (uint32_t)(par); uint32_t _d;                \
    asm volatile("{\n\t.reg .pred p;\n\t"                                         \
        "mbarrier.try_wait.parity.acquire.cta.shared::cta.b64 p, [%1], %2;\n\t"   \
        "selp.b32 %0, 1, 0, p;\n\t}" : "=r"(_d) : "r"(_m), "r"(_p) : "memory");   \
    if (!_d) {                                                                    \
        asm volatile("{\n\t.reg .pred P1;\n\t"                                    \
            "WL_%=:\n\t"                                                          \
            "mbarrier.try_wait.parity.acquire.cta.shared::cta.b64 P1, [%0], %1, 0x989680;\n\t" \
            "@P1 bra.uni WD_%=;\n\tbra.uni WL_%=;\n\tWD_%=:\n\t}"                 \
            :: "r"(_m), "r"(_p) : "memory");                                      \
    }                                                                             \
} while (0)
#define FENCE_ASYNC() asm volatile("fence.proxy.async.shared::cta;" ::: "memory")
__device__ __forceinline__ void bulk_cp(uint32_t dst, const void* src, uint32_t bytes,
                                        uint32_t mbar) {
    asm volatile("cp.async.bulk.shared::cta.global.mbarrier::complete_tx::bytes "
                 "[%0], [%1], %2, [%3];"
                 :: "r"(dst), "l"(src), "r"(bytes), "r"(mbar) : "memory");
}

// ---------------- prep kernel ----------------
// blocks [0,2048): input -> [b][y][xblock:16][1KB] f16 pairs, swizzled so a
//   linear bulk-copy lands LDSM-conflict-free in smem (key = x&7).
// blocks [2048,2192): weights -> swizzled [tap][c:64 x 128B] f16 tiles.
__global__ void prep(const float* __restrict__ inp, const float* __restrict__ conv) {
    const int tid = threadIdx.x;
    if (blockIdx.x >= 2048) {
        if (blockIdx.x == 2048 && tid == 0) g_ctr = GRID_MAIN;
        int i = (blockIdx.x - 2048) * 256 + tid;
        if (i < 9 * 64 * 64) {
            int o = i & 63, c = (i >> 6) & 63, tap = i >> 12;
            __half h = __float2half(conv[(o * 64 + c) * 9 + tap]);
            unsigned short* img = (unsigned short*)g_wimg;
            uint32_t byte = (uint32_t)(c * 128 + ((((o >> 3) ^ (c & 7))) << 4) + (o & 7) * 2);
            img[(tap * 8192 + byte) >> 1] = __half_as_ushort(h);
        }
        return;
    }
    __shared__ float tile[64][65];
    const int blk = blockIdx.x;
    const int half = blk & 1, y = (blk >> 1) & 127, b = blk >> 8;
    const int x0 = half * 64;
    #pragma unroll
    for (int i = 0; i < 16; ++i) {
        int idx = i * 256 + tid;
        int c = idx >> 6, x = idx & 63;
        tile[c][x] = inp[((b * CH + c) * HDIM + y) * WDIM + x0 + x];
    }
    __syncthreads();
    #pragma unroll
    for (int i = 0; i < 8; ++i) {
        int idx = i * 256 + tid;
        int x = (idx >> 5) + x0, cw = idx & 31;
        __half h0 = __float2half(tile[2 * (idx & 31)][idx >> 5]);
        __half h1 = __float2half(tile[2 * (idx & 31) + 1][idx >> 5]);
        uint32_t v = (uint32_t)__half_as_ushort(h0) | ((uint32_t)__half_as_ushort(h1) << 16);
        int u = cw >> 2;
        int dst = ((b * HDIM + y) << 12) + ((x >> 3) << 8) + ((x & 7) << 5)
                + (((u ^ (x & 7))) << 2) + (cw & 3);
        g_xt[dst] = v;
    }
}

// ---------------- main persistent kernel ----------------
__global__ __launch_bounds__(NTHREADS, 1)
void instconv_mma(const float* __restrict__ mask,
                  const float* __restrict__ bias,
                  float* __restrict__ out) {
    extern __shared__ char smem[];
    const uint32_t sb = smem_u32(smem);
    const int tid = threadIdx.x;
    const int wid = tid >> 5;
    const int lane = tid & 31;
    const int g = lane >> 2;
    const int t2 = (lane & 3) * 2;
    const int p0 = wid * 16;          // 16-px group
    const int lane15 = lane & 15;
    const int laneHi = lane >> 4;

    volatile int* sCtrl = (volatile int*)(smem + OFF_CTRL);
    const uint32_t mbarA[2] = { sb + OFF_CTRL + 16, sb + OFF_CTRL + 24 };

    // stage weights once (cp.async group)
    {
        const uint4* src = g_wimg;
        #pragma unroll 4
        for (int i = tid; i < W_BYTES / 16; i += NTHREADS)
            cpasync16(sb + OFF_W + i * 16, src + i);
        asm volatile("cp.async.commit_group;" ::: "memory");
    }
    if (tid < 64) ((float*)(smem + OFF_B))[tid] = bias[tid];
    if (tid == 0) { MBARRIER_INIT(mbarA[0], 1); MBARRIER_INIT(mbarA[1], 1); }
    const float* sB = (const float*)(smem + OFF_B);

    // W lane-constant swizzled addresses
    const uint32_t wLane = sb + OFF_W + (uint32_t)(lane15 * 128);
    uint32_t wcs[4];
    #pragma unroll
    for (int nb2 = 0; nb2 < 4; ++nb2)
        wcs[nb2] = (uint32_t)((((nb2 * 2 + laneHi) ^ (lane & 7))) << 4);

    // ---- prologue: stage first tile ----
    int t = blockIdx.x;
    {
        const int b = t >> 6, y0 = (t & 63) * 2;
        if (tid == 0) {
            FENCE_ASYNC();
            MBARRIER_EXPECT_TX(mbarA[0], 4 * 16384);
            #pragma unroll
            for (int s = 0; s < 4; ++s) {
                int ys = y0 - 1 + s; ys = ys < 0 ? 0 : (ys > 127 ? 127 : ys);
                bulk_cp(sb + OFF_X + s * SLOT_B + 128,
                        g_xt + ((size_t)(b * HDIM + ys) << 12), 16384, mbarA[0]);
            }
        }
        float* sM0 = (float*)(smem + OFF_M);
        for (int i = tid; i < 528; i += NTHREADS) {
            int r = i / 132, xi = i - r * 132;
            int ys = y0 + r - 1, xs = xi - 1;
            float v = -1.0f;
            if ((unsigned)ys < (unsigned)HDIM && (unsigned)xs < (unsigned)WDIM)
                v = mask[(b * HDIM + ys) * WDIM + xs];
            sM0[i] = v;
        }
        if (tid == 0) sCtrl[0] = atomicAdd(&g_ctr, 1);
    }
    asm volatile("cp.async.wait_group 0;" ::: "memory");
    __syncthreads();   // W + mask + sCtrl visible

    int ph0 = 0, ph1 = 0;
    int buf = 0;

    for (;;) {
        const int b = t >> 6, y0 = (t & 63) * 2;

        // wait X staged for this tile
        if (buf == 0) { MBARRIER_WAIT_PARITY(mbarA[0], ph0); ph0 ^= 1; }
        else          { MBARRIER_WAIT_PARITY(mbarA[1], ph1); ph1 ^= 1; }

        const int tn = sCtrl[0];
        const bool have_next = tn < NTILES;
        __syncthreads();   // everyone has tn before thread0 overwrites sCtrl

        // prefetch next tile into other buffer
        const int bn = tn >> 6, yn0 = (tn & 63) * 2;
        if (tid == 0 && have_next) {
            FENCE_ASYNC();
            MBARRIER_EXPECT_TX(mbarA[buf ^ 1], 4 * 16384);
            #pragma unroll
            for (int s = 0; s < 4; ++s) {
                int ys = yn0 - 1 + s; ys = ys < 0 ? 0 : (ys > 127 ? 127 : ys);
                bulk_cp(sb + OFF_X + ((buf ^ 1) * 4 + s) * SLOT_B + 128,
                        g_xt + ((size_t)(bn * HDIM + ys) << 12), 16384, mbarA[buf ^ 1]);
            }
        }
        // mask prefetch for next tile into registers (STS at end of tile)
        float mr[3];
        #pragma unroll
        for (int j = 0; j < 3; ++j) {
            mr[j] = -1.0f;
            int i = tid + j * 256;
            if (have_next && i < 528) {
                int r = i / 132, xi = i - r * 132;
                int ys = yn0 + r - 1, xs = xi - 1;
                if ((unsigned)ys < (unsigned)HDIM && (unsigned)xs < (unsigned)WDIM)
                    mr[j] = mask[(bn * HDIM + ys) * WDIM + xs];
            }
        }
        if (tid == 0) sCtrl[0] = atomicAdd(&g_ctr, 1);

        const float* sMb = (const float*)(smem + OFF_M + buf * MASK_BUF);
        // centers: row r center at window row 1+r, px p0+g (+8)
        const float c00 = sMb[1 * 132 + 1 + p0 + g];
        const float c01 = sMb[1 * 132 + 1 + p0 + g + 8];
        const float c10 = sMb[2 * 132 + 1 + p0 + g];
        const float c11 = sMb[2 * 132 + 1 + p0 + g + 8];

        float D0[8][4], D1[8][4];
        #pragma unroll
        for (int nb = 0; nb < 8; ++nb)
            #pragma unroll
            for (int j = 0; j < 4; ++j) { D0[nb][j] = 0.0f; D1[nb][j] = 0.0f; }

        #pragma unroll
        for (int ky = 0; ky < 3; ++ky) {
            const uint32_t baseA0 = sb + OFF_X + (uint32_t)((buf * 4 + ky) * SLOT_B);
            const uint32_t baseA1 = baseA0 + SLOT_B;
            const float* mT0 = sMb + ky * 132;        // tap row for out-row 0
            const float* mT1 = sMb + (ky + 1) * 132;  // tap row for out-row 1

            #pragma unroll 1
            for (int kx = 0; kx < 3; ++kx) {
                const uint32_t mk00 = (mT0[p0 + g + kx]     == c00) ? 0xFFFFFFFFu : 0u;
                const uint32_t mk01 = (mT0[p0 + g + 8 + kx] == c01) ? 0xFFFFFFFFu : 0u;
                const uint32_t mk10 = (mT1[p0 + g + kx]     == c10) ? 0xFFFFFFFFu : 0u;
                const uint32_t mk11 = (mT1[p0 + g + 8 + kx] == c11) ? 0xFFFFFFFFu : 0u;

                const int xi = p0 + lane15 + kx;
                const uint32_t rowb = (uint32_t)(xi * 128);
                const int xorm = (lane15 + kx + 7) & 7;
                const uint32_t wTap = wLane + (uint32_t)((ky * 3 + kx) * 8192);

                #pragma unroll
                for (int k = 0; k < 4; ++k) {
                    const uint32_t colA = (uint32_t)(((k * 2 + laneHi) ^ xorm) << 4);
                    uint32_t a0[4], a1[4];
                    ldsm_x4(baseA0 + rowb + colA, a0);
                    ldsm_x4(baseA1 + rowb + colA, a1);
                    a0[0] &= mk00; a0[2] &= mk00; a0[1] &= mk01; a0[3] &= mk01;
                    a1[0] &= mk10; a1[2] &= mk10; a1[1] &= mk11; a1[3] &= mk11;

                    const uint32_t wk = wTap + (uint32_t)(k * 2048);
                    #pragma unroll
                    for (int nb2 = 0; nb2 < 4; ++nb2) {
                        uint32_t b0, b1, b2, b3;
                        ldsm_x4t(wk + wcs[nb2], b0, b1, b2, b3);
                        mma_f16(D0[2 * nb2],     a0, b0, b1);
                        mma_f16(D0[2 * nb2 + 1], a0, b2, b3);
                        mma_f16(D1[2 * nb2],     a1, b0, b1);
                        mma_f16(D1[2 * nb2 + 1], a1, b2, b3);
                    }
                }
            }
        }

        // ---- epilogue: inv factors, then 2 row passes through smem ----
        float inv00, inv01, inv10, inv11;
        {
            float n00 = 0, n01 = 0, n10 = 0, n11 = 0;
            #pragma unroll
            for (int ky2 = 0; ky2 < 3; ++ky2)
                #pragma unroll
                for (int kx2 = 0; kx2 < 3; ++kx2) {
                    n00 += (sMb[ky2 * 132 + p0 + g + kx2]           == c00) ? 1.0f : 0.0f;
                    n01 += (sMb[ky2 * 132 + p0 + g + 8 + kx2]       == c01) ? 1.0f : 0.0f;
                    n10 += (sMb[(ky2 + 1) * 132 + p0 + g + kx2]     == c10) ? 1.0f : 0.0f;
                    n11 += (sMb[(ky2 + 1) * 132 + p0 + g + 8 + kx2] == c11) ? 1.0f : 0.0f;
                }
            inv00 = 9.0f / n00; inv01 = 9.0f / n01;
            inv10 = 9.0f / n10; inv11 = 9.0f / n11;
        }

        float* Dsm = (float*)(smem + OFF_X + buf * 4 * SLOT_B);   // [64][132] f32
        // pass r = 0
        __syncthreads();   // all LDSM on buf done
        #pragma unroll
        for (int nb = 0; nb < 8; ++nb) {
            const int o0 = nb * 8 + t2;
            const float b0v = sB[o0], b1v = sB[o0 + 1];
            Dsm[o0 * 132 + p0 + g]           = D0[nb][0] * inv00 + b0v;
            Dsm[(o0 + 1) * 132 + p0 + g]     = D0[nb][1] * inv00 + b1v;
            Dsm[o0 * 132 + p0 + g + 8]       = D0[nb][2] * inv01 + b0v;
            Dsm[(o0 + 1) * 132 + p0 + g + 8] = D0[nb][3] * inv01 + b1v;
        }
        __syncthreads();
        {
            const int o = tid >> 2, q = tid & 3;
            const float4* src = (const float4*)(Dsm + o * 132 + q * 32);
            float4* dst = (float4*)(out + (((size_t)b * OCN + o) * HDIM + y0) * WDIM + q * 32);
            #pragma unroll
            for (int j = 0; j < 8; ++j) dst[j] = src[j];
            if (tid < 128)
                out[OUT_MASK_OFF + (b * HDIM + y0) * WDIM + tid] = sMb[1 * 132 + 1 + tid];
        }
        // pass r = 1
        __syncthreads();
        #pragma unroll
        for (int nb = 0; nb < 8; ++nb) {
            const int o0 = nb * 8 + t2;
            const float b0v = sB[o0], b1v = sB[o0 + 1];
            Dsm[o0 * 132 + p0 + g]           = D1[nb][0] * inv10 + b0v;
            Dsm[(o0 + 1) * 132 + p0 + g]     = D1[nb][1] * inv10 + b1v;
            Dsm[o0 * 132 + p0 + g + 8]       = D1[nb][2] * inv11 + b0v;
            Dsm[(o0 + 1) * 132 + p0 + g + 8] = D1[nb][3] * inv11 + b1v;
        }
        __syncthreads();
        {
            const int o = tid >> 2, q = tid & 3;
            const float4* src = (const float4*)(Dsm + o * 132 + q * 32);
            float4* dst = (float4*)(out + (((size_t)b * OCN + o) * HDIM + y0 + 1) * WDIM + q * 32);
            #pragma unroll
            for (int j = 0; j < 8; ++j) dst[j] = src[j];
            if (tid < 128)
                out[OUT_MASK_OFF + (b * HDIM + y0 + 1) * WDIM + tid] = sMb[2 * 132 + 1 + tid];
        }

        // store prefetched mask for next tile
        {
            float* sMn = (float*)(smem + OFF_M + (buf ^ 1) * MASK_BUF);
            #pragma unroll
            for (int j = 0; j < 3; ++j) {
                int i = tid + j * 256;
                if (i < 528) sMn[i] = mr[j];
            }
        }
        __syncthreads();   // mask + Dsm consumption ordered before next iter

        if (!have_next) break;
        t = tn;
        buf ^= 1;
    }
}

extern "C" void kernel_launch(void* const* d_in, const int* in_sizes, int n_in,
                              void* d_out, int out_size) {
    const float* inp  = (const float*)d_in[0];
    const float* mask = (const float*)d_in[1];
    const float* conv = (const float*)d_in[2];
    const float* bias = (const float*)d_in[3];
    float* out = (float*)d_out;
    (void)in_sizes; (void)n_in; (void)out_size;

    cudaFuncSetAttribute(instconv_mma,
                         cudaFuncAttributeMaxDynamicSharedMemorySize, SMEM_TOTAL);

    prep<<<2048 + 144, 256>>>(inp, conv);
    instconv_mma<<<GRID_MAIN, NTHREADS, SMEM_TOTAL>>>(mask, bias, out);
}

// round 10
// speedup vs baseline: 1.0767x; 1.0767x over previous
#include <cuda_runtime.h>
#include <cuda_fp16.h>
#include <cstdint>

// InstanceConv via warp-level mma.sync f16 GEMM (compute_103-safe).
// Round 10: 512 threads (16 warps/SM), warps split OC; 2-row x 128-px tiles;
// per-k 2 A-ldsm + 2 W-ldsm per 8 mma (smem wf == tensor cyc);
// cp.async.bulk staging of pre-swizzled input; atomic work stealing.
// B=8, C=64, OC=64, H=W=128, K=3, pad=1.

#define BATCH 8
#define CH 64
#define OCN 64
#define HDIM 128
#define WDIM 128
#define NTILES 512                   // 2-row x 128-px tiles
#define GRID_MAIN 152
#define NTHREADS 512
#define OUT_MASK_OFF (BATCH * OCN * HDIM * WDIM)   // 8388608

// ---- smem layout (bytes) ----
#define OFF_W 0
#define W_BYTES (9 * 8192)               // 73728: [tap] 64(c)x64(o) f16, swizzled
#define SLOT_B 16640                     // one X row slot: [xi:130][c:64] f16 swz
#define OFF_X (OFF_W + W_BYTES)          // 73728: 2 buffers x 4 slots
#define OFF_M (OFF_X + 8 * SLOT_B)       // 206848: 2 x mask [4][132] f32
#define MASK_BUF 2112
#define OFF_B (OFF_M + 2 * MASK_BUF)     // 211072: bias
#define OFF_CTRL (OFF_B + 256)           // 211328: [0]=next tile u32; +16/+24 mbars
#define SMEM_TOTAL (OFF_CTRL + 32)       // 211360

__device__ uint32_t g_xt[BATCH * HDIM * WDIM * 32];  // [b][y][xb:16][1KB swizzled]
__device__ uint4 g_wimg[W_BYTES / 16];
__device__ int g_ctr;

__device__ __forceinline__ uint32_t smem_u32(const void* p) {
    uint32_t a;
    asm("{ .reg .u64 t; cvta.to.shared.u64 t, %1; cvt.u32.u64 %0, t; }" : "=r"(a) : "l"(p));
    return a;
}
__device__ __forceinline__ void ldsm_x4(uint32_t addr, uint32_t* r) {
    asm volatile("ldmatrix.sync.aligned.m8n8.x4.shared.b16 {%0,%1,%2,%3}, [%4];"
                 : "=r"(r[0]), "=r"(r[1]), "=r"(r[2]), "=r"(r[3]) : "r"(addr));
}
__device__ __forceinline__ void ldsm_x4t(uint32_t addr, uint32_t& r0, uint32_t& r1,
                                         uint32_t& r2, uint32_t& r3) {
    asm volatile("ldmatrix.sync.aligned.m8n8.x4.trans.shared.b16 {%0,%1,%2,%3}, [%4];"
                 : "=r"(r0), "=r"(r1), "=r"(r2), "=r"(r3) : "r"(addr));
}
__device__ __forceinline__ void mma_f16(float* d, const uint32_t* a, uint32_t b0, uint32_t b1) {
    asm volatile("mma.sync.aligned.m16n8k16.row.col.f32.f16.f16.f32 "
                 "{%0,%1,%2,%3}, {%4,%5,%6,%7}, {%8,%9}, {%0,%1,%2,%3};"
                 : "+f"(d[0]), "+f"(d[1]), "+f"(d[2]), "+f"(d[3])
                 : "r"(a[0]), "r"(a[1]), "r"(a[2]), "r"(a[3]), "r"(b0), "r"(b1));
}
__device__ __forceinline__ void cpasync16(uint32_t d, const void* s) {
    asm volatile("cp.async.ca.shared.global [%0], [%1], 16;"
                 :: "r"(d), "l"(s) : "memory");
}
#define MBARRIER_INIT(a, n) \
    asm volatile("mbarrier.init.shared.b64 [%0], %1;" :: "r"(a), "r"((uint32_t)(n)) : "memory")
#define MBARRIER_EXPECT_TX(a, tx) \
    asm volatile("mbarrier.arrive.expect_tx.shared.b64 _, [%0], %1;" \
                 :: "r"(a), "r"((uint32_t)(tx)) : "memory")
#define MBARRIER_WAIT_PARITY(a, par) do {                                         \
    uint32_t _m = (a); uint32_t _p = (uint32_t)(par); uint32_t _d;                \
    asm volatile("{\n\t.reg .pred p;\n\t"                                         \
        "mbarrier.try_wait.parity.acquire.cta.shared::cta.b64 p, [%1], %2;\n\t"   \
        "selp.b32 %0, 1, 0, p;\n\t}" : "=r"(_d) : "r"(_m), "r"(_p) : "memory");   \
    if (!_d) {                                                                    \
        asm volatile("{\n\t.reg .pred P1;\n\t"                                    \
            "WL_%=:\n\t"                                                          \
            "mbarrier.try_wait.parity.acquire.cta.shared::cta.b64 P1, [%0], %1, 0x989680;\n\t" \
            "@P1 bra.uni WD_%=;\n\tbra.uni WL_%=;\n\tWD_%=:\n\t}"                 \
            :: "r"(_m), "r"(_p) : "memory");                                      \
    }                                                                             \
} while (0)
#define FENCE_ASYNC() asm volatile("fence.proxy.async.shared::cta;" ::: "memory")
__device__ __forceinline__ void bulk_cp(uint32_t dst, const void* src, uint32_t bytes,
                                        uint32_t mbar) {
    asm volatile("cp.async.bulk.shared::cta.global.mbarrier::complete_tx::bytes "
                 "[%0], [%1], %2, [%3];"
                 :: "r"(dst), "l"(src), "r"(bytes), "r"(mbar) : "memory");
}

// ---------------- prep kernel ----------------
// blocks [0,2048): input -> [b][y][xblock:16][1KB] f16 pairs, swizzled so a
//   linear bulk-copy lands LDSM-conflict-free in smem (key = x&7).
// blocks [2048,2192): weights -> swizzled [tap][c:64 x 128B] f16 tiles.
__global__ void prep(const float* __restrict__ inp, const float* __restrict__ conv) {
    const int tid = threadIdx.x;
    if (blockIdx.x >= 2048) {
        if (blockIdx.x == 2048 && tid == 0) g_ctr = GRID_MAIN;
        int i = (blockIdx.x - 2048) * 256 + tid;
        if (i < 9 * 64 * 64) {
            int o = i & 63, c = (i >> 6) & 63, tap = i >> 12;
            __half h = __float2half(conv[(o * 64 + c) * 9 + tap]);
            unsigned short* img = (unsigned short*)g_wimg;
            uint32_t byte = (uint32_t)(c * 128 + ((((o >> 3) ^ (c & 7))) << 4) + (o & 7) * 2);
            img[(tap * 8192 + byte) >> 1] = __half_as_ushort(h);
        }
        return;
    }
    __shared__ float tile[64][65];
    const int blk = blockIdx.x;
    const int half = blk & 1, y = (blk >> 1) & 127, b = blk >> 8;
    const int x0 = half * 64;
    #pragma unroll
    for (int i = 0; i < 16; ++i) {
        int idx = i * 256 + tid;
        int c = idx >> 6, x = idx & 63;
        tile[c][x] = inp[((b * CH + c) * HDIM + y) * WDIM + x0 + x];
    }
    __syncthreads();
    #pragma unroll
    for (int i = 0; i < 8; ++i) {
        int idx = i * 256 + tid;
        int x = (idx >> 5) + x0, cw = idx & 31;
        __half h0 = __float2half(tile[2 * (idx & 31)][idx >> 5]);
        __half h1 = __float2half(tile[2 * (idx & 31) + 1][idx >> 5]);
        uint32_t v = (uint32_t)__half_as_ushort(h0) | ((uint32_t)__half_as_ushort(h1) << 16);
        int u = cw >> 2;
        int dst = ((b * HDIM + y) << 12) + ((x >> 3) << 8) + ((x & 7) << 5)
                + (((u ^ (x & 7))) << 2) + (cw & 3);
        g_xt[dst] = v;
    }
}

// ---------------- main persistent kernel ----------------
__global__ __launch_bounds__(NTHREADS, 1)
void instconv_mma(const float* __restrict__ mask,
                  const float* __restrict__ bias,
                  float* __restrict__ out) {
    extern __shared__ char smem[];
    const uint32_t sb = smem_u32(smem);
    const int tid = threadIdx.x;
    const int wid = tid >> 5;
    const int lane = tid & 31;
    const int g = lane >> 2;
    const int t2 = (lane & 3) * 2;
    const int h = wid >> 3;           // oc half (0: oc<32, 1: oc>=32)
    const int p0 = (wid & 7) * 16;    // 16-px group
    const int lane15 = lane & 15;
    const int laneHi = lane >> 4;

    volatile int* sCtrl = (volatile int*)(smem + OFF_CTRL);
    const uint32_t mbarA[2] = { sb + OFF_CTRL + 16, sb + OFF_CTRL + 24 };

    // stage weights once (cp.async group)
    {
        const uint4* src = g_wimg;
        #pragma unroll 4
        for (int i = tid; i < W_BYTES / 16; i += NTHREADS)
            cpasync16(sb + OFF_W + i * 16, src + i);
        asm volatile("cp.async.commit_group;" ::: "memory");
    }
    if (tid < 64) ((float*)(smem + OFF_B))[tid] = bias[tid];
    if (tid == 0) { MBARRIER_INIT(mbarA[0], 1); MBARRIER_INIT(mbarA[1], 1); }
    const float* sB = (const float*)(smem + OFF_B);

    // W lane-constant swizzled col offsets for this oc half (2 x 16-oc blocks)
    const uint32_t wLane = sb + OFF_W + (uint32_t)(lane15 * 128);
    uint32_t wcs[2];
    #pragma unroll
    for (int j = 0; j < 2; ++j)
        wcs[j] = (uint32_t)(((((2 * h + j) * 2 + laneHi) ^ (lane & 7))) << 4);

    // ---- prologue: stage first tile ----
    int t = blockIdx.x;
    {
        const int b = t >> 6, y0 = (t & 63) * 2;
        if (tid == 0) {
            FENCE_ASYNC();
            MBARRIER_EXPECT_TX(mbarA[0], 4 * 16384);
            #pragma unroll
            for (int s = 0; s < 4; ++s) {
                int ys = y0 - 1 + s; ys = ys < 0 ? 0 : (ys > 127 ? 127 : ys);
                bulk_cp(sb + OFF_X + s * SLOT_B + 128,
                        g_xt + ((size_t)(b * HDIM + ys) << 12), 16384, mbarA[0]);
            }
        }
        float* sM0 = (float*)(smem + OFF_M);
        for (int i = tid; i < 528; i += NTHREADS) {
            int r = i / 132, xi = i - r * 132;
            int ys = y0 + r - 1, xs = xi - 1;
            float v = -1.0f;
            if ((unsigned)ys < (unsigned)HDIM && (unsigned)xs < (unsigned)WDIM)
                v = mask[(b * HDIM + ys) * WDIM + xs];
            sM0[i] = v;
        }
        if (tid == 0) sCtrl[0] = atomicAdd(&g_ctr, 1);
    }
    asm volatile("cp.async.wait_group 0;" ::: "memory");
    __syncthreads();   // W + mask + sCtrl visible

    int ph0 = 0, ph1 = 0;
    int buf = 0;

    for (;;) {
        const int b = t >> 6, y0 = (t & 63) * 2;

        // wait X staged for this tile
        if (buf == 0) { MBARRIER_WAIT_PARITY(mbarA[0], ph0); ph0 ^= 1; }
        else          { MBARRIER_WAIT_PARITY(mbarA[1], ph1); ph1 ^= 1; }

        const int tn = sCtrl[0];
        const bool have_next = tn < NTILES;
        __syncthreads();   // everyone has tn before thread0 overwrites sCtrl

        // prefetch next tile into other buffer
        const int bn = tn >> 6, yn0 = (tn & 63) * 2;
        if (tid == 0 && have_next) {
            FENCE_ASYNC();
            MBARRIER_EXPECT_TX(mbarA[buf ^ 1], 4 * 16384);
            #pragma unroll
            for (int s = 0; s < 4; ++s) {
                int ys = yn0 - 1 + s; ys = ys < 0 ? 0 : (ys > 127 ? 127 : ys);
                bulk_cp(sb + OFF_X + ((buf ^ 1) * 4 + s) * SLOT_B + 128,
                        g_xt + ((size_t)(bn * HDIM + ys) << 12), 16384, mbarA[buf ^ 1]);
            }
        }
        // mask prefetch for next tile into registers (STS at end of tile)
        float mr[2];
        #pragma unroll
        for (int j = 0; j < 2; ++j) {
            mr[j] = -1.0f;
            int i = tid + j * NTHREADS;
            if (have_next && i < 528) {
                int r = i / 132, xi = i - r * 132;
                int ys = yn0 + r - 1, xs = xi - 1;
                if ((unsigned)ys < (unsigned)HDIM && (unsigned)xs < (unsigned)WDIM)
                    mr[j] = mask[(bn * HDIM + ys) * WDIM + xs];
            }
        }
        if (tid == 0) sCtrl[0] = atomicAdd(&g_ctr, 1);

        const float* sMb = (const float*)(smem + OFF_M + buf * MASK_BUF);
        const float c00 = sMb[1 * 132 + 1 + p0 + g];
        const float c01 = sMb[1 * 132 + 1 + p0 + g + 8];
        const float c10 = sMb[2 * 132 + 1 + p0 + g];
        const float c11 = sMb[2 * 132 + 1 + p0 + g + 8];

        float D0[4][4], D1[4][4];
        #pragma unroll
        for (int nb = 0; nb < 4; ++nb)
            #pragma unroll
            for (int j = 0; j < 4; ++j) { D0[nb][j] = 0.0f; D1[nb][j] = 0.0f; }

        #pragma unroll
        for (int ky = 0; ky < 3; ++ky) {
            const uint32_t baseA0 = sb + OFF_X + (uint32_t)((buf * 4 + ky) * SLOT_B);
            const uint32_t baseA1 = baseA0 + SLOT_B;
            const float* mT0 = sMb + ky * 132;        // tap row for out-row 0
            const float* mT1 = sMb + (ky + 1) * 132;  // tap row for out-row 1

            #pragma unroll 1
            for (int kx = 0; kx < 3; ++kx) {
                const uint32_t mk00 = (mT0[p0 + g + kx]     == c00) ? 0xFFFFFFFFu : 0u;
                const uint32_t mk01 = (mT0[p0 + g + 8 + kx] == c01) ? 0xFFFFFFFFu : 0u;
                const uint32_t mk10 = (mT1[p0 + g + kx]     == c10) ? 0xFFFFFFFFu : 0u;
                const uint32_t mk11 = (mT1[p0 + g + 8 + kx] == c11) ? 0xFFFFFFFFu : 0u;

                const int xi = p0 + lane15 + kx;
                const uint32_t rowb = (uint32_t)(xi * 128);
                const int xorm = (lane15 + kx + 7) & 7;
                const uint32_t wTap = wLane + (uint32_t)((ky * 3 + kx) * 8192);

                #pragma unroll
                for (int k = 0; k < 4; ++k) {
                    const uint32_t colA = (uint32_t)(((k * 2 + laneHi) ^ xorm) << 4);
                    uint32_t a0[4], a1[4];
                    ldsm_x4(baseA0 + rowb + colA, a0);
                    ldsm_x4(baseA1 + rowb + colA, a1);
                    a0[0] &= mk00; a0[2] &= mk00; a0[1] &= mk01; a0[3] &= mk01;
                    a1[0] &= mk10; a1[2] &= mk10; a1[1] &= mk11; a1[3] &= mk11;

                    const uint32_t wk = wTap + (uint32_t)(k * 2048);
                    #pragma unroll
                    for (int j = 0; j < 2; ++j) {
                        uint32_t b0, b1, b2, b3;
                        ldsm_x4t(wk + wcs[j], b0, b1, b2, b3);
                        mma_f16(D0[2 * j],     a0, b0, b1);
                        mma_f16(D0[2 * j + 1], a0, b2, b3);
                        mma_f16(D1[2 * j],     a1, b0, b1);
                        mma_f16(D1[2 * j + 1], a1, b2, b3);
                    }
                }
            }
        }

        // ---- epilogue ----
        float inv00, inv01, inv10, inv11;
        {
            float n00 = 0, n01 = 0, n10 = 0, n11 = 0;
            #pragma unroll
            for (int ky2 = 0; ky2 < 3; ++ky2)
                #pragma unroll
                for (int kx2 = 0; kx2 < 3; ++kx2) {
                    n00 += (sMb[ky2 * 132 + p0 + g + kx2]           == c00) ? 1.0f : 0.0f;
                    n01 += (sMb[ky2 * 132 + p0 + g + 8 + kx2]       == c01) ? 1.0f : 0.0f;
                    n10 += (sMb[(ky2 + 1) * 132 + p0 + g + kx2]     == c10) ? 1.0f : 0.0f;
                    n11 += (sMb[(ky2 + 1) * 132 + p0 + g + 8 + kx2] == c11) ? 1.0f : 0.0f;
                }
            inv00 = 9.0f / n00; inv01 = 9.0f / n01;
            inv10 = 9.0f / n10; inv11 = 9.0f / n11;
        }

        float* Dsm = (float*)(smem + OFF_X + buf * 4 * SLOT_B);   // [64][132] f32
        // pass r = 0
        __syncthreads();   // all LDSM on buf done
        #pragma unroll
        for (int nb = 0; nb < 4; ++nb) {
            const int o0 = h * 32 + nb * 8 + t2;
            const float b0v = sB[o0], b1v = sB[o0 + 1];
            Dsm[o0 * 132 + p0 + g]           = D0[nb][0] * inv00 + b0v;
            Dsm[(o0 + 1) * 132 + p0 + g]     = D0[nb][1] * inv00 + b1v;
            Dsm[o0 * 132 + p0 + g + 8]       = D0[nb][2] * inv01 + b0v;
            Dsm[(o0 + 1) * 132 + p0 + g + 8] = D0[nb][3] * inv01 + b1v;
        }
        __syncthreads();
        {
            const int o = tid >> 3, q = tid & 7;
            const float4* src = (const float4*)(Dsm + o * 132 + q * 16);
            float4* dst = (float4*)(out + (((size_t)b * OCN + o) * HDIM + y0) * WDIM + q * 16);
            #pragma unroll
            for (int j = 0; j < 4; ++j) dst[j] = src[j];
            if (tid < 128)
                out[OUT_MASK_OFF + (b * HDIM + y0) * WDIM + tid] = sMb[1 * 132 + 1 + tid];
        }
        // pass r = 1
        __syncthreads();
        #pragma unroll
        for (int nb = 0; nb < 4; ++nb) {
            const int o0 = h * 32 + nb * 8 + t2;
            const float b0v = sB[o0], b1v = sB[o0 + 1];
            Dsm[o0 * 132 + p0 + g]           = D1[nb][0] * inv10 + b0v;
            Dsm[(o0 + 1) * 132 + p0 + g]     = D1[nb][1] * inv10 + b1v;
            Dsm[o0 * 132 + p0 + g + 8]       = D1[nb][2] * inv11 + b0v;
            Dsm[(o0 + 1) * 132 + p0 + g + 8] = D1[nb][3] * inv11 + b1v;
        }
        __syncthreads();
        {
            const int o = tid >> 3, q = tid & 7;
            const float4* src = (const float4*)(Dsm + o * 132 + q * 16);
            float4* dst = (float4*)(out + (((size_t)b * OCN + o) * HDIM + y0 + 1) * WDIM + q * 16);
            #pragma unroll
            for (int j = 0; j < 4; ++j) dst[j] = src[j];
            if (tid < 128)
                out[OUT_MASK_OFF + (b * HDIM + y0 + 1) * WDIM + tid] = sMb[2 * 132 + 1 + tid];
        }

        // store prefetched mask for next tile
        {
            float* sMn = (float*)(smem + OFF_M + (buf ^ 1) * MASK_BUF);
            #pragma unroll
            for (int j = 0; j < 2; ++j) {
                int i = tid + j * NTHREADS;
                if (i < 528) sMn[i] = mr[j];
            }
        }
        __syncthreads();   // mask + Dsm consumption ordered before next iter

        if (!have_next) break;
        t = tn;
        buf ^= 1;
    }
}

extern "C" void kernel_launch(void* const* d_in, const int* in_sizes, int n_in,
                              void* d_out, int out_size) {
    const float* inp  = (const float*)d_in[0];
    const float* mask = (const float*)d_in[1];
    const float* conv = (const float*)d_in[2];
    const float* bias = (const float*)d_in[3];
    float* out = (float*)d_out;
    (void)in_sizes; (void)n_in; (void)out_size;

    cudaFuncSetAttribute(instconv_mma,
                         cudaFuncAttributeMaxDynamicSharedMemorySize, SMEM_TOTAL);

    prep<<<2048 + 144, 256>>>(inp, conv);
    instconv_mma<<<GRID_MAIN, NTHREADS, SMEM_TOTAL>>>(mask, bias, out);
}

// round 11
// speedup vs baseline: 1.0812x; 1.0041x over previous
#include <cuda_runtime.h>
#include <cuda_fp16.h>
#include <cstdint>

// InstanceConv via warp-level mma.sync f16 GEMM (compute_103-safe).
// Round 11: 4-row x 128-px tiles; warp = 4 rows x 16 px x 32 oc
// (6 ldsm per 16 mma -> smem 0.75 of tensor); 16 warps; single-buffer X
// with staging overlapped by epilogue; atomic work stealing.
// B=8, C=64, OC=64, H=W=128, K=3, pad=1.

#define BATCH 8
#define CH 64
#define OCN 64
#define HDIM 128
#define WDIM 128
#define NTILES 256                   // 4-row x 128-px tiles
#define GRID_MAIN 152
#define NTHREADS 512
#define OUT_MASK_OFF (BATCH * OCN * HDIM * WDIM)   // 8388608

// ---- smem layout (bytes) ----
#define OFF_W 0
#define W_BYTES (9 * 8192)               // 73728: [tap] 64(c)x64(o) f16, swizzled
#define SLOT_B 16640                     // one X row slot (130*128)
#define OFF_X (OFF_W + W_BYTES)          // 73728: 6 slots
#define OFF_D (OFF_X + 6 * SLOT_B)       // 173568: Dsm [64][132] f32 = 33792
#define OFF_M (OFF_D + 33792)            // 207360: 2 x mask [6][132] f32
#define MASK_BUF 3168
#define OFF_B (OFF_M + 2 * MASK_BUF)     // 213696: bias
#define OFF_CTRL (OFF_B + 256)           // 213952: [0]=next tile; +16 mbar
#define SMEM_TOTAL (OFF_CTRL + 32)       // 213984

__device__ uint32_t g_xt[BATCH * HDIM * WDIM * 32];  // [b][y][xb:16][1KB swizzled]
__device__ uint4 g_wimg[W_BYTES / 16];
__device__ int g_ctr;

__device__ __forceinline__ uint32_t smem_u32(const void* p) {
    uint32_t a;
    asm("{ .reg .u64 t; cvta.to.shared.u64 t, %1; cvt.u32.u64 %0, t; }" : "=r"(a) : "l"(p));
    return a;
}
__device__ __forceinline__ void ldsm_x4(uint32_t addr, uint32_t* r) {
    asm volatile("ldmatrix.sync.aligned.m8n8.x4.shared.b16 {%0,%1,%2,%3}, [%4];"
                 : "=r"(r[0]), "=r"(r[1]), "=r"(r[2]), "=r"(r[3]) : "r"(addr));
}
__device__ __forceinline__ void ldsm_x4t(uint32_t addr, uint32_t& r0, uint32_t& r1,
                                         uint32_t& r2, uint32_t& r3) {
    asm volatile("ldmatrix.sync.aligned.m8n8.x4.trans.shared.b16 {%0,%1,%2,%3}, [%4];"
                 : "=r"(r0), "=r"(r1), "=r"(r2), "=r"(r3) : "r"(addr));
}
__device__ __forceinline__ void mma_f16(float* d, const uint32_t* a, uint32_t b0, uint32_t b1) {
    asm volatile("mma.sync.aligned.m16n8k16.row.col.f32.f16.f16.f32 "
                 "{%0,%1,%2,%3}, {%4,%5,%6,%7}, {%8,%9}, {%0,%1,%2,%3};"
                 : "+f"(d[0]), "+f"(d[1]), "+f"(d[2]), "+f"(d[3])
                 : "r"(a[0]), "r"(a[1]), "r"(a[2]), "r"(a[3]), "r"(b0), "r"(b1));
}
__device__ __forceinline__ void cpasync16(uint32_t d, const void* s) {
    asm volatile("cp.async.ca.shared.global [%0], [%1], 16;"
                 :: "r"(d), "l"(s) : "memory");
}
#define MBARRIER_INIT(a, n) \
    asm volatile("mbarrier.init.shared.b64 [%0], %1;" :: "r"(a), "r"((uint32_t)(n)) : "memory")
#define MBARRIER_EXPECT_TX(a, tx) \
    asm volatile("mbarrier.arrive.expect_tx.shared.b64 _, [%0], %1;" \
                 :: "r"(a), "r"((uint32_t)(tx)) : "memory")
#define MBARRIER_WAIT_PARITY(a, par) do {                                         \
    uint32_t _m = (a); uint32_t _p = (uint32_t)(par); uint32_t _d;                \
    asm volatile("{\n\t.reg .pred p;\n\t"                                         \
        "mbarrier.try_wait.parity.acquire.cta.shared::cta.b64 p, [%1], %2;\n\t"   \
        "selp.b32 %0, 1, 0, p;\n\t}" : "=r"(_d) : "r"(_m), "r"(_p) : "memory");   \
    if (!_d) {                                                                    \
        asm volatile("{\n\t.reg .pred P1;\n\t"                                    \
            "WL_%=:\n\t"                                                          \
            "mbarrier.try_wait.parity.acquire.cta.shared::cta.b64 P1, [%0], %1, 0x989680;\n\t" \
            "@P1 bra.uni WD_%=;\n\tbra.uni WL_%=;\n\tWD_%=:\n\t}"                 \
            :: "r"(_m), "r"(_p) : "memory");                                      \
    }                                                                             \
} while (0)
#define FENCE_ASYNC() asm volatile("fence.proxy.async.shared::cta;" ::: "memory")
__device__ __forceinline__ void bulk_cp(uint32_t dst, const void* src, uint32_t bytes,
                                        uint32_t mbar) {
    asm volatile("cp.async.bulk.shared::cta.global.mbarrier::complete_tx::bytes "
                 "[%0], [%1], %2, [%3];"
                 :: "r"(dst), "l"(src), "r"(bytes), "r"(mbar) : "memory");
}

// ---------------- prep kernel ----------------
__global__ void prep(const float* __restrict__ inp, const float* __restrict__ conv) {
    const int tid = threadIdx.x;
    if (blockIdx.x >= 2048) {
        if (blockIdx.x == 2048 && tid == 0) g_ctr = GRID_MAIN;
        int i = (blockIdx.x - 2048) * 256 + tid;
        if (i < 9 * 64 * 64) {
            int o = i & 63, c = (i >> 6) & 63, tap = i >> 12;
            __half h = __float2half(conv[(o * 64 + c) * 9 + tap]);
            unsigned short* img = (unsigned short*)g_wimg;
            uint32_t byte = (uint32_t)(c * 128 + ((((o >> 3) ^ (c & 7))) << 4) + (o & 7) * 2);
            img[(tap * 8192 + byte) >> 1] = __half_as_ushort(h);
        }
        return;
    }
    __shared__ float tile[64][65];
    const int blk = blockIdx.x;
    const int half = blk & 1, y = (blk >> 1) & 127, b = blk >> 8;
    const int x0 = half * 64;
    #pragma unroll
    for (int i = 0; i < 16; ++i) {
        int idx = i * 256 + tid;
        int c = idx >> 6, x = idx & 63;
        tile[c][x] = inp[((b * CH + c) * HDIM + y) * WDIM + x0 + x];
    }
    __syncthreads();
    #pragma unroll
    for (int i = 0; i < 8; ++i) {
        int idx = i * 256 + tid;
        int x = (idx >> 5) + x0, cw = idx & 31;
        __half h0 = __float2half(tile[2 * (idx & 31)][idx >> 5]);
        __half h1 = __float2half(tile[2 * (idx & 31) + 1][idx >> 5]);
        uint32_t v = (uint32_t)__half_as_ushort(h0) | ((uint32_t)__half_as_ushort(h1) << 16);
        int u = cw >> 2;
        int dst = ((b * HDIM + y) << 12) + ((x >> 3) << 8) + ((x & 7) << 5)
                + (((u ^ (x & 7))) << 2) + (cw & 3);
        g_xt[dst] = v;
    }
}

// ---------------- main persistent kernel ----------------
__global__ __launch_bounds__(NTHREADS, 1)
void instconv_mma(const float* __restrict__ mask,
                  const float* __restrict__ bias,
                  float* __restrict__ out) {
    extern __shared__ char smem[];
    const uint32_t sb = smem_u32(smem);
    const int tid = threadIdx.x;
    const int wid = tid >> 5;
    const int lane = tid & 31;
    const int g = lane >> 2;
    const int t2 = (lane & 3) * 2;
    const int h = wid >> 3;           // oc half
    const int p0 = (wid & 7) * 16;    // 16-px group
    const int lane15 = lane & 15;
    const int laneHi = lane >> 4;

    volatile int* sCtrl = (volatile int*)(smem + OFF_CTRL);
    const uint32_t mbar = sb + OFF_CTRL + 16;

    // stage weights once (cp.async group)
    {
        const uint4* src = g_wimg;
        #pragma unroll 4
        for (int i = tid; i < W_BYTES / 16; i += NTHREADS)
            cpasync16(sb + OFF_W + i * 16, src + i);
        asm volatile("cp.async.commit_group;" ::: "memory");
    }
    if (tid < 64) ((float*)(smem + OFF_B))[tid] = bias[tid];
    if (tid == 0) MBARRIER_INIT(mbar, 1);
    const float* sB = (const float*)(smem + OFF_B);

    const uint32_t wLane = sb + OFF_W + (uint32_t)(lane15 * 128);
    uint32_t wcs[2];
    #pragma unroll
    for (int j = 0; j < 2; ++j)
        wcs[j] = (uint32_t)(((((h * 2 + j) * 2 + laneHi) ^ (lane & 7))) << 4);

    // ---- prologue: stage first tile ----
    int t = blockIdx.x;
    {
        const int b = t >> 5, y0 = (t & 31) * 4;
        if (tid == 0) {
            FENCE_ASYNC();
            MBARRIER_EXPECT_TX(mbar, 6 * 16384);
            #pragma unroll
            for (int s = 0; s < 6; ++s) {
                int ys = y0 - 1 + s; ys = ys < 0 ? 0 : (ys > 127 ? 127 : ys);
                bulk_cp(sb + OFF_X + s * SLOT_B + 128,
                        g_xt + ((size_t)(b * HDIM + ys) << 12), 16384, mbar);
            }
        }
        float* sM0 = (float*)(smem + OFF_M);
        for (int i = tid; i < 792; i += NTHREADS) {
            int r = i / 132, xi = i - r * 132;
            int ys = y0 + r - 1, xs = xi - 1;
            float v = -1.0f;
            if ((unsigned)ys < (unsigned)HDIM && (unsigned)xs < (unsigned)WDIM)
                v = mask[(b * HDIM + ys) * WDIM + xs];
            sM0[i] = v;
        }
        if (tid == 0) sCtrl[0] = atomicAdd(&g_ctr, 1);
    }
    asm volatile("cp.async.wait_group 0;" ::: "memory");
    __syncthreads();   // W + mask + sCtrl visible

    int ph = 0, buf = 0;

    for (;;) {
        const int b = t >> 5, y0 = (t & 31) * 4;

        MBARRIER_WAIT_PARITY(mbar, ph); ph ^= 1;
        const int tn = sCtrl[0];
        const bool have_next = tn < NTILES;
        __syncthreads();
        if (tid == 0) sCtrl[0] = atomicAdd(&g_ctr, 1);

        const float* sMb = (const float*)(smem + OFF_M + buf * MASK_BUF);
        float c0[4][2];
        #pragma unroll
        for (int r = 0; r < 4; ++r) {
            c0[r][0] = sMb[(r + 1) * 132 + 1 + p0 + g];
            c0[r][1] = sMb[(r + 1) * 132 + 1 + p0 + g + 8];
        }

        float D[16][4];   // [r*4 + j*2 + m][4]
        #pragma unroll
        for (int q = 0; q < 16; ++q)
            #pragma unroll
            for (int j = 0; j < 4; ++j) D[q][j] = 0.0f;

        #pragma unroll
        for (int ky = 0; ky < 3; ++ky) {
            #pragma unroll 1
            for (int kx = 0; kx < 3; ++kx) {
                uint32_t mk[4][2];
                #pragma unroll
                for (int r = 0; r < 4; ++r) {
                    const float* mT = sMb + (r + ky) * 132;
                    mk[r][0] = (mT[p0 + g + kx]     == c0[r][0]) ? 0xFFFFFFFFu : 0u;
                    mk[r][1] = (mT[p0 + g + 8 + kx] == c0[r][1]) ? 0xFFFFFFFFu : 0u;
                }
                const uint32_t rowb = (uint32_t)((p0 + lane15 + kx) * 128);
                const int xorm = (lane15 + kx + 7) & 7;
                const uint32_t wTap = wLane + (uint32_t)((ky * 3 + kx) * 8192);
                const uint32_t aKy = sb + OFF_X + (uint32_t)(ky * SLOT_B) + rowb;

                #pragma unroll
                for (int k = 0; k < 4; ++k) {
                    const uint32_t colA = (uint32_t)(((k * 2 + laneHi) ^ xorm) << 4);
                    uint32_t a[4][4];
                    #pragma unroll
                    for (int r = 0; r < 4; ++r)
                        ldsm_x4(aKy + (uint32_t)(r * SLOT_B) + colA, a[r]);
                    #pragma unroll
                    for (int r = 0; r < 4; ++r) {
                        a[r][0] &= mk[r][0]; a[r][2] &= mk[r][0];
                        a[r][1] &= mk[r][1]; a[r][3] &= mk[r][1];
                    }
                    const uint32_t wk = wTap + (uint32_t)(k * 2048);
                    #pragma unroll
                    for (int j = 0; j < 2; ++j) {
                        uint32_t b0, b1, b2, b3;
                        ldsm_x4t(wk + wcs[j], b0, b1, b2, b3);
                        #pragma unroll
                        for (int r = 0; r < 4; ++r) {
                            mma_f16(D[r * 4 + j * 2],     a[r], b0, b1);
                            mma_f16(D[r * 4 + j * 2 + 1], a[r], b2, b3);
                        }
                    }
                }
            }
        }
        __syncthreads();   // all slot reads done

        // issue next-tile staging now; it overlaps the epilogue below
        const int bn = tn >> 5, yn0 = (tn & 31) * 4;
        if (tid == 0 && have_next) {
            FENCE_ASYNC();
            MBARRIER_EXPECT_TX(mbar, 6 * 16384);
            #pragma unroll
            for (int s = 0; s < 6; ++s) {
                int ys = yn0 - 1 + s; ys = ys < 0 ? 0 : (ys > 127 ? 127 : ys);
                bulk_cp(sb + OFF_X + s * SLOT_B + 128,
                        g_xt + ((size_t)(bn * HDIM + ys) << 12), 16384, mbar);
            }
        }
        // next-tile mask loads (latency hidden by epilogue)
        float mr0 = -1.0f, mr1 = -1.0f;
        if (have_next) {
            int i0 = tid, i1 = tid + NTHREADS;
            {
                int r = i0 / 132, xi = i0 - r * 132;
                int ys = yn0 + r - 1, xs = xi - 1;
                if ((unsigned)ys < (unsigned)HDIM && (unsigned)xs < (unsigned)WDIM)
                    mr0 = mask[(bn * HDIM + ys) * WDIM + xs];
            }
            if (i1 < 792) {
                int r = i1 / 132, xi = i1 - r * 132;
                int ys = yn0 + r - 1, xs = xi - 1;
                if ((unsigned)ys < (unsigned)HDIM && (unsigned)xs < (unsigned)WDIM)
                    mr1 = mask[(bn * HDIM + ys) * WDIM + xs];
            }
        }

        // inv factors
        float inv[4][2];
        #pragma unroll
        for (int r = 0; r < 4; ++r) {
            float n0 = 0.0f, n1 = 0.0f;
            #pragma unroll
            for (int ky2 = 0; ky2 < 3; ++ky2) {
                const float* mT = sMb + (r + ky2) * 132;
                #pragma unroll
                for (int kx2 = 0; kx2 < 3; ++kx2) {
                    n0 += (mT[p0 + g + kx2]     == c0[r][0]) ? 1.0f : 0.0f;
                    n1 += (mT[p0 + g + 8 + kx2] == c0[r][1]) ? 1.0f : 0.0f;
                }
            }
            inv[r][0] = 9.0f / n0; inv[r][1] = 9.0f / n1;   // cnt >= 1
        }

        // epilogue: 4 row passes through Dsm
        float* Dsm = (float*)(smem + OFF_D);   // [64][132] f32
        #pragma unroll
        for (int r = 0; r < 4; ++r) {
            #pragma unroll
            for (int j2 = 0; j2 < 4; ++j2) {
                const int o0 = h * 32 + (j2 >> 1) * 16 + (j2 & 1) * 8 + t2;
                const float b0v = sB[o0], b1v = sB[o0 + 1];
                const float* Dr = D[r * 4 + j2];
                Dsm[o0 * 132 + p0 + g]           = Dr[0] * inv[r][0] + b0v;
                Dsm[(o0 + 1) * 132 + p0 + g]     = Dr[1] * inv[r][0] + b1v;
                Dsm[o0 * 132 + p0 + g + 8]       = Dr[2] * inv[r][1] + b0v;
                Dsm[(o0 + 1) * 132 + p0 + g + 8] = Dr[3] * inv[r][1] + b1v;
            }
            __syncthreads();
            {
                const int o = tid >> 3, q = tid & 7;
                const float4* src = (const float4*)(Dsm + o * 132 + q * 16);
                float4* dst = (float4*)(out + (((size_t)b * OCN + o) * HDIM + y0 + r) * WDIM + q * 16);
                #pragma unroll
                for (int j = 0; j < 4; ++j) dst[j] = src[j];
            }
            __syncthreads();
        }
        // mask passthrough (4 rows x 128 px = 512 threads)
        {
            const int r = tid >> 7, px = tid & 127;
            out[OUT_MASK_OFF + (b * HDIM + y0 + r) * WDIM + px] = sMb[(r + 1) * 132 + 1 + px];
        }
        // store prefetched mask for next tile
        {
            float* sMn = (float*)(smem + OFF_M + (buf ^ 1) * MASK_BUF);
            sMn[tid] = mr0;
            if (tid + NTHREADS < 792) sMn[tid + NTHREADS] = mr1;
        }
        __syncthreads();

        if (!have_next) break;
        t = tn;
        buf ^= 1;
    }
}

extern "C" void kernel_launch(void* const* d_in, const int* in_sizes, int n_in,
                              void* d_out, int out_size) {
    const float* inp  = (const float*)d_in[0];
    const float* mask = (const float*)d_in[1];
    const float* conv = (const float*)d_in[2];
    const float* bias = (const float*)d_in[3];
    float* out = (float*)d_out;
    (void)in_sizes; (void)n_in; (void)out_size;

    cudaFuncSetAttribute(instconv_mma,
                         cudaFuncAttributeMaxDynamicSharedMemorySize, SMEM_TOTAL);

    prep<<<2048 + 144, 256>>>(inp, conv);
    instconv_mma<<<GRID_MAIN, NTHREADS, SMEM_TOTAL>>>(mask, bias, out);
}